// round 1
// baseline (speedup 1.0000x reference)
#include <cuda_runtime.h>
#include <math.h>

#define NN 100000
#define EE 3200000
#define DD 256
#define LN_EPS 1e-5f

// ---------------- scratch (static device globals; no runtime alloc) ----------
__device__ float g_h  [(size_t)NN * DD];   // layer input (h0 = safe(x))
__device__ float g_xw [(size_t)NN * DD];   // h @ W
__device__ float g_agg[(size_t)NN * DD];   // aggregated messages
__device__ float g_deg[NN];
__device__ float g_dis[NN];
__device__ float g_ew [EE];
__device__ float g_norm[EE];
__device__ int   g_is64;

__device__ __forceinline__ float fsafe(float v) { return isfinite(v) ? v : 0.0f; }

// ---------------- edge-index dtype detection --------------------------------
// Reference asks for int64 but JAX without x64 silently produces int32.
// If the buffer is int32, reading the first 64 entries as int64 packs two
// random indices < 1e5 into one word -> value >= 2^32 with overwhelming
// probability. Deterministic w.r.t. inputs.
__global__ void k_detect(const void* ei) {
    const long long* p = (const long long*)ei;
    int ok64 = 1;
    for (int i = 0; i < 64; i++) {
        long long v = p[i];
        if (v < 0 || v >= NN) ok64 = 0;
    }
    g_is64 = ok64;
}

__device__ __forceinline__ int edge_at(const void* ei, long long idx, int is64) {
    if (is64) return (int)((const long long*)ei)[idx];
    return ((const int*)ei)[idx];
}

// ---------------- prep kernels ----------------------------------------------
__global__ void k_zero_deg() {
    int i = blockIdx.x * blockDim.x + threadIdx.x;
    if (i < NN) g_deg[i] = 0.0f;
}

__global__ void k_deg(const void* __restrict__ ei, const float* __restrict__ ew) {
    long long e = (long long)blockIdx.x * blockDim.x + threadIdx.x;
    if (e >= EE) return;
    int is64 = g_is64;
    float w = fsafe(ew[e]);
    w = fmaxf(fabsf(w), 1e-6f);
    g_ew[e] = w;
    int col = edge_at(ei, (long long)EE + e, is64);
    atomicAdd(&g_deg[col], w);
}

__global__ void k_dis() {
    int i = blockIdx.x * blockDim.x + threadIdx.x;
    if (i < NN) g_dis[i] = rsqrtf(g_deg[i] + 1.0f);
}

__global__ void k_norm(const void* __restrict__ ei) {
    long long e = (long long)blockIdx.x * blockDim.x + threadIdx.x;
    if (e >= EE) return;
    int is64 = g_is64;
    int row = edge_at(ei, e, is64);
    int col = edge_at(ei, (long long)EE + e, is64);
    g_norm[e] = g_dis[row] * g_ew[e] * g_dis[col];
}

__global__ void k_safe_copy(const float* __restrict__ x) {
    long long i = (long long)blockIdx.x * blockDim.x + threadIdx.x;  // float4 idx
    if (i >= (long long)NN * DD / 4) return;
    float4 v = ((const float4*)x)[i];
    v.x = fsafe(v.x); v.y = fsafe(v.y); v.z = fsafe(v.z); v.w = fsafe(v.w);
    ((float4*)g_h)[i] = v;
}

// ---------------- SGEMM: C[M,256] = A[M,256] @ B[256,256] -------------------
// Classic 64x64x16 tiling, 4x4 microtile, 256 threads.
__global__ __launch_bounds__(256) void k_gemm(const float* __restrict__ A,
                                              const float* __restrict__ B,
                                              float* __restrict__ C) {
    const int BM = 64, BN = 64, BK = 16;
    __shared__ float As[BK][BM];
    __shared__ float Bs[BK][BN];

    int tid = threadIdx.x;
    int tx = tid % 16;          // N tile coord (x4)
    int ty = tid / 16;          // M tile coord (x4)
    int blockRow = blockIdx.x * BM;
    int blockCol = blockIdx.y * BN;

    // load mapping
    int arow = tid / 4;          // 0..63
    int acol = (tid % 4) * 4;    // 0,4,8,12
    int brow = tid / 16;         // 0..15
    int bcol = (tid % 16) * 4;   // 0..60

    float acc[4][4] = {};

    for (int k0 = 0; k0 < 256; k0 += BK) {
        float4 a;
        int gr = blockRow + arow;
        if (gr < NN) a = *(const float4*)&A[(size_t)gr * 256 + k0 + acol];
        else         a = make_float4(0.f, 0.f, 0.f, 0.f);
        As[acol + 0][arow] = a.x;
        As[acol + 1][arow] = a.y;
        As[acol + 2][arow] = a.z;
        As[acol + 3][arow] = a.w;

        float4 b = *(const float4*)&B[(size_t)(k0 + brow) * 256 + blockCol + bcol];
        *(float4*)&Bs[brow][bcol] = b;
        __syncthreads();

#pragma unroll
        for (int k = 0; k < BK; k++) {
            float4 am = *(const float4*)&As[k][ty * 4];
            float4 bn = *(const float4*)&Bs[k][tx * 4];
            float amv[4] = {am.x, am.y, am.z, am.w};
            float bnv[4] = {bn.x, bn.y, bn.z, bn.w};
#pragma unroll
            for (int i = 0; i < 4; i++)
#pragma unroll
                for (int j = 0; j < 4; j++)
                    acc[i][j] += amv[i] * bnv[j];
        }
        __syncthreads();
    }

#pragma unroll
    for (int i = 0; i < 4; i++) {
        int gr = blockRow + ty * 4 + i;
        if (gr < NN) {
            float4 o = make_float4(acc[i][0], acc[i][1], acc[i][2], acc[i][3]);
            *(float4*)&C[(size_t)gr * 256 + blockCol + tx * 4] = o;
        }
    }
}

// ---------------- agg init: agg = dis^2 * xw + bias (self-loop + bias) ------
__global__ void k_agginit(const float* __restrict__ bias) {
    long long i = (long long)blockIdx.x * blockDim.x + threadIdx.x;  // float4 idx
    if (i >= (long long)NN * DD / 4) return;
    int row = (int)(i >> 6);          // /64 float4s per row
    int c4  = ((int)i & 63) * 4;
    float s = g_dis[row];
    s = s * s;
    float4 v = ((const float4*)g_xw)[i];
    float4 b = *(const float4*)&bias[c4];
    float4 o = make_float4(fmaf(s, v.x, b.x), fmaf(s, v.y, b.y),
                           fmaf(s, v.z, b.z), fmaf(s, v.w, b.w));
    ((float4*)g_agg)[i] = o;
}

// ---------------- scatter: agg[col] += norm[e] * xw[row] --------------------
// 64 threads per edge, one float4 each (256 floats/row). Vector reduction.
__global__ __launch_bounds__(256) void k_scatter(const void* __restrict__ ei) {
    int lane = threadIdx.x & 63;                       // float4 slot within row
    long long e = (long long)blockIdx.x * (blockDim.x >> 6) + (threadIdx.x >> 6);
    if (e >= EE) return;
    int is64 = g_is64;
    int row, col;
    if (is64) {
        const long long* p = (const long long*)ei;
        row = (int)p[e];
        col = (int)p[(long long)EE + e];
    } else {
        const int* p = (const int*)ei;
        row = p[e];
        col = p[EE + e];
    }
    float nrm = g_norm[e];
    const float4* src = (const float4*)&g_xw[(size_t)row * DD];
    float4 v = __ldg(&src[lane]);
    float4* dst = (float4*)&g_agg[(size_t)col * DD] + lane;
    asm volatile("red.global.add.v4.f32 [%0], {%1, %2, %3, %4};"
                 :: "l"(dst), "f"(nrm * v.x), "f"(nrm * v.y),
                    "f"(nrm * v.z), "f"(nrm * v.w)
                 : "memory");
}

// ---------------- post: safe -> LN -> relu -> + residual -> safe ------------
// One warp per row (D=256 -> 8 floats/lane as 2 float4).
__global__ __launch_bounds__(256) void k_post(const float* __restrict__ lng,
                                              const float* __restrict__ lnb,
                                              const float* __restrict__ hres,
                                              float* __restrict__ out) {
    int warp = (blockIdx.x * blockDim.x + threadIdx.x) >> 5;
    int lane = threadIdx.x & 31;
    if (warp >= NN) return;

    const float4* a = (const float4*)&g_agg[(size_t)warp * DD];
    float4 v0 = a[lane];
    float4 v1 = a[lane + 32];
    v0.x = fsafe(v0.x); v0.y = fsafe(v0.y); v0.z = fsafe(v0.z); v0.w = fsafe(v0.w);
    v1.x = fsafe(v1.x); v1.y = fsafe(v1.y); v1.z = fsafe(v1.z); v1.w = fsafe(v1.w);

    float s  = v0.x + v0.y + v0.z + v0.w + v1.x + v1.y + v1.z + v1.w;
    float sq = v0.x * v0.x + v0.y * v0.y + v0.z * v0.z + v0.w * v0.w +
               v1.x * v1.x + v1.y * v1.y + v1.z * v1.z + v1.w * v1.w;
#pragma unroll
    for (int o = 16; o > 0; o >>= 1) {
        s  += __shfl_xor_sync(0xFFFFFFFFu, s,  o);
        sq += __shfl_xor_sync(0xFFFFFFFFu, sq, o);
    }
    float mu  = s * (1.0f / 256.0f);
    float var = sq * (1.0f / 256.0f) - mu * mu;
    float inv = rsqrtf(var + LN_EPS);

    int d0 = lane * 4;
    int d1 = (lane + 32) * 4;
    float4 g0 = *(const float4*)&lng[d0];
    float4 g1 = *(const float4*)&lng[d1];
    float4 b0 = *(const float4*)&lnb[d0];
    float4 b1 = *(const float4*)&lnb[d1];
    const float4* hr = (const float4*)&hres[(size_t)warp * DD];
    float4 r0 = hr[lane];
    float4 r1 = hr[lane + 32];

    float4 o0, o1;
    o0.x = fsafe(fmaxf(fsafe((v0.x - mu) * inv * g0.x + b0.x), 0.f) + fsafe(r0.x));
    o0.y = fsafe(fmaxf(fsafe((v0.y - mu) * inv * g0.y + b0.y), 0.f) + fsafe(r0.y));
    o0.z = fsafe(fmaxf(fsafe((v0.z - mu) * inv * g0.z + b0.z), 0.f) + fsafe(r0.z));
    o0.w = fsafe(fmaxf(fsafe((v0.w - mu) * inv * g0.w + b0.w), 0.f) + fsafe(r0.w));
    o1.x = fsafe(fmaxf(fsafe((v1.x - mu) * inv * g1.x + b1.x), 0.f) + fsafe(r1.x));
    o1.y = fsafe(fmaxf(fsafe((v1.y - mu) * inv * g1.y + b1.y), 0.f) + fsafe(r1.y));
    o1.z = fsafe(fmaxf(fsafe((v1.z - mu) * inv * g1.z + b1.z), 0.f) + fsafe(r1.z));
    o1.w = fsafe(fmaxf(fsafe((v1.w - mu) * inv * g1.w + b1.w), 0.f) + fsafe(r1.w));

    float4* op = (float4*)&out[(size_t)warp * DD];
    op[lane]      = o0;
    op[lane + 32] = o1;
}

// ---------------- host launch ------------------------------------------------
extern "C" void kernel_launch(void* const* d_in, const int* in_sizes, int n_in,
                              void* d_out, int out_size) {
    const float* x   = (const float*)d_in[0];
    const void*  ei  = d_in[1];                 // int64 or int32, detected on device
    const float* ew  = (const float*)d_in[2];
    const float* W1  = (const float*)d_in[3];
    const float* b1  = (const float*)d_in[4];
    const float* lg1 = (const float*)d_in[5];
    const float* lb1 = (const float*)d_in[6];
    const float* W2  = (const float*)d_in[7];
    const float* b2  = (const float*)d_in[8];
    const float* lg2 = (const float*)d_in[9];
    const float* lb2 = (const float*)d_in[10];
    float* out = (float*)d_out;

    void *p_h = nullptr, *p_xw = nullptr;
    cudaGetSymbolAddress(&p_h, g_h);
    cudaGetSymbolAddress(&p_xw, g_xw);
    const float* h0 = (const float*)p_h;
    float* xw = (float*)p_xw;

    const long long nd4 = (long long)NN * DD / 4;

    k_detect<<<1, 1>>>(ei);
    k_zero_deg<<<(NN + 255) / 256, 256>>>();
    k_deg<<<(EE + 255) / 256, 256>>>(ei, ew);
    k_dis<<<(NN + 255) / 256, 256>>>();
    k_norm<<<(EE + 255) / 256, 256>>>(ei);
    k_safe_copy<<<(int)((nd4 + 255) / 256), 256>>>(x);

    dim3 gemm_grid((NN + 63) / 64, 256 / 64);

    // ---- layer 1 ----
    k_gemm<<<gemm_grid, 256>>>(h0, W1, xw);
    k_agginit<<<(int)((nd4 + 255) / 256), 256>>>(b1);
    k_scatter<<<(EE + 3) / 4, 256>>>(ei);
    k_post<<<(NN * 32 + 255) / 256, 256>>>(lg1, lb1, h0, out);   // h1 -> d_out

    // ---- layer 2 ----
    k_gemm<<<gemm_grid, 256>>>(out, W2, xw);
    k_agginit<<<(int)((nd4 + 255) / 256), 256>>>(b2);
    k_scatter<<<(EE + 3) / 4, 256>>>(ei);
    k_post<<<(NN * 32 + 255) / 256, 256>>>(lg2, lb2, out, out);  // final -> d_out
}

// round 9
// speedup vs baseline: 3.0510x; 3.0510x over previous
#include <cuda_runtime.h>
#include <stdint.h>
#include <math.h>

#define NN 100000
#define EE 3200000
#define DD 256
#define LN_EPS 1e-5f

// ---------------- scratch (static device globals; no runtime alloc) ----------
__device__ __align__(16) float g_h  [(size_t)NN * DD];   // h0 = safe(x)
__device__ __align__(16) float g_xw [(size_t)NN * DD];   // h @ W
__device__ float g_deg[NN];
__device__ float g_dis[NN];
__device__ float g_ew [EE];
__device__ int   g_cnt[NN];
__device__ int   g_rs [NN + 1];
__device__ int   g_cur[NN];
__device__ int   g_src[EE];      // CSR: source node per incoming edge, grouped by col
__device__ float g_nrm[EE];      // CSR: edge norm coefficient
__device__ int   g_is64;

__device__ __forceinline__ float fsafe(float v) { return isfinite(v) ? v : 0.0f; }

// ---------------- edge-index dtype detection --------------------------------
__global__ void k_detect(const void* ei) {
    const long long* p = (const long long*)ei;
    int ok64 = 1;
    for (int i = 0; i < 64; i++) {
        long long v = p[i];
        if (v < 0 || v >= NN) ok64 = 0;
    }
    g_is64 = ok64;
}

// ---------------- prep -------------------------------------------------------
__global__ void k_zero() {
    int i = blockIdx.x * blockDim.x + threadIdx.x;
    if (i < NN) { g_deg[i] = 0.0f; g_cnt[i] = 0; }
}

// clean edge weight, weighted degree (col), CSR counts (col)
__global__ void k_deg(const void* __restrict__ ei, const float* __restrict__ ew) {
    long long e = (long long)blockIdx.x * blockDim.x + threadIdx.x;
    if (e >= EE) return;
    int is64 = g_is64;
    float w = fsafe(ew[e]);
    w = fmaxf(fabsf(w), 1e-6f);
    g_ew[e] = w;
    int col = is64 ? (int)((const long long*)ei)[(long long)EE + e]
                   : ((const int*)ei)[EE + e];
    atomicAdd(&g_deg[col], w);
    atomicAdd(&g_cnt[col], 1);
}

__global__ void k_dis() {
    int i = blockIdx.x * blockDim.x + threadIdx.x;
    if (i < NN) g_dis[i] = rsqrtf(g_deg[i] + 1.0f);
}

// single-block exclusive scan of g_cnt -> g_rs, g_cur
__global__ __launch_bounds__(1024) void k_scan() {
    __shared__ int wsum[32];
    __shared__ int carry;
    int t = threadIdx.x, lane = t & 31, w = t >> 5;
    if (t == 0) carry = 0;
    __syncthreads();
    for (int base = 0; base < NN; base += 1024) {
        int v = (base + t < NN) ? g_cnt[base + t] : 0;
        int incl = v;
#pragma unroll
        for (int o = 1; o < 32; o <<= 1) {
            int n = __shfl_up_sync(0xFFFFFFFFu, incl, o);
            if (lane >= o) incl += n;
        }
        if (lane == 31) wsum[w] = incl;
        __syncthreads();
        if (w == 0) {
            int s = wsum[lane];
#pragma unroll
            for (int o = 1; o < 32; o <<= 1) {
                int n = __shfl_up_sync(0xFFFFFFFFu, s, o);
                if (lane >= o) s += n;
            }
            wsum[lane] = s;
        }
        __syncthreads();
        int woff = (w == 0) ? 0 : wsum[w - 1];
        int excl = carry + woff + incl - v;
        if (base + t < NN) { g_rs[base + t] = excl; g_cur[base + t] = excl; }
        __syncthreads();
        if (t == 0) carry += wsum[31];
        __syncthreads();
    }
    if (t == 0) g_rs[NN] = carry;
}

// fill CSR: slot per edge grouped by destination (col)
__global__ void k_fill(const void* __restrict__ ei) {
    long long e = (long long)blockIdx.x * blockDim.x + threadIdx.x;
    if (e >= EE) return;
    int is64 = g_is64;
    int row, col;
    if (is64) {
        const long long* p = (const long long*)ei;
        row = (int)p[e]; col = (int)p[(long long)EE + e];
    } else {
        const int* p = (const int*)ei;
        row = p[e]; col = p[EE + e];
    }
    float nrm = g_dis[row] * g_ew[e] * g_dis[col];
    int slot = atomicAdd(&g_cur[col], 1);
    g_src[slot] = row;
    g_nrm[slot] = nrm;
}

__global__ void k_safe_copy(const float* __restrict__ x) {
    long long i = (long long)blockIdx.x * blockDim.x + threadIdx.x;  // float4 idx
    if (i >= (long long)NN * DD / 4) return;
    float4 v = ((const float4*)x)[i];
    v.x = fsafe(v.x); v.y = fsafe(v.y); v.z = fsafe(v.z); v.w = fsafe(v.w);
    ((float4*)g_h)[i] = v;
}

// ---------------- TF32 tensor-core GEMM: C[M,256] = A[M,256] @ B[256,256] ---
// Block tile 128x64x32, 8 warps (4x2), warp tile 32x32, mma.m16n8k8.tf32.
__device__ __forceinline__ float tf32r(float x) {
    uint32_t u;
    asm("cvt.rna.tf32.f32 %0, %1;" : "=r"(u) : "f"(x));
    return __uint_as_float(u);
}

#define GBM 128
#define GBN 64
#define GBK 32

__global__ __launch_bounds__(256) void k_gemm_tf32(const float* __restrict__ A,
                                                   const float* __restrict__ B,
                                                   float* __restrict__ C, int M) {
    __shared__ float As[GBM][GBK + 4];   // stride 36: conflict-free frag loads
    __shared__ float Bs[GBK][GBN + 4];   // stride 68
    int tid  = threadIdx.x;
    int warp = tid >> 5, lane = tid & 31;
    int wm = warp & 3, wn = warp >> 2;
    int rowbase = blockIdx.x * GBM;
    int colbase = blockIdx.y * GBN;
    int g = lane >> 2, tg = lane & 3;

    float acc[2][4][4];
#pragma unroll
    for (int a = 0; a < 2; a++)
#pragma unroll
        for (int b = 0; b < 4; b++)
#pragma unroll
            for (int c = 0; c < 4; c++) acc[a][b][c] = 0.0f;

    for (int k0 = 0; k0 < 256; k0 += GBK) {
#pragma unroll
        for (int p = 0; p < 4; p++) {
            int r = (tid >> 3) + p * 32;
            int gr = rowbase + r;
            float4 a = (gr < M) ? *(const float4*)&A[(size_t)gr * 256 + k0 + (tid & 7) * 4]
                                : make_float4(0.f, 0.f, 0.f, 0.f);
            a.x = tf32r(a.x); a.y = tf32r(a.y); a.z = tf32r(a.z); a.w = tf32r(a.w);
            *(float4*)&As[r][(tid & 7) * 4] = a;
        }
#pragma unroll
        for (int p = 0; p < 2; p++) {
            int r = (tid >> 4) + p * 16;
            float4 b = *(const float4*)&B[(size_t)(k0 + r) * 256 + colbase + (tid & 15) * 4];
            b.x = tf32r(b.x); b.y = tf32r(b.y); b.z = tf32r(b.z); b.w = tf32r(b.w);
            *(float4*)&Bs[r][(tid & 15) * 4] = b;
        }
        __syncthreads();
#pragma unroll
        for (int kk = 0; kk < GBK; kk += 8) {
            uint32_t afr[2][4];
#pragma unroll
            for (int mt = 0; mt < 2; mt++) {
                int r0 = wm * 32 + mt * 16 + g;
                int c0 = kk + tg;
                afr[mt][0] = __float_as_uint(As[r0][c0]);
                afr[mt][1] = __float_as_uint(As[r0 + 8][c0]);
                afr[mt][2] = __float_as_uint(As[r0][c0 + 4]);
                afr[mt][3] = __float_as_uint(As[r0 + 8][c0 + 4]);
            }
            uint32_t bfr[4][2];
#pragma unroll
            for (int nt = 0; nt < 4; nt++) {
                int c0 = wn * 32 + nt * 8 + g;
                int r0 = kk + tg;
                bfr[nt][0] = __float_as_uint(Bs[r0][c0]);
                bfr[nt][1] = __float_as_uint(Bs[r0 + 4][c0]);
            }
#pragma unroll
            for (int mt = 0; mt < 2; mt++)
#pragma unroll
                for (int nt = 0; nt < 4; nt++) {
                    asm volatile(
                        "mma.sync.aligned.m16n8k8.row.col.f32.tf32.tf32.f32 "
                        "{%0,%1,%2,%3}, {%4,%5,%6,%7}, {%8,%9}, {%0,%1,%2,%3};"
                        : "+f"(acc[mt][nt][0]), "+f"(acc[mt][nt][1]),
                          "+f"(acc[mt][nt][2]), "+f"(acc[mt][nt][3])
                        : "r"(afr[mt][0]), "r"(afr[mt][1]),
                          "r"(afr[mt][2]), "r"(afr[mt][3]),
                          "r"(bfr[nt][0]), "r"(bfr[nt][1]));
                }
        }
        __syncthreads();
    }

#pragma unroll
    for (int mt = 0; mt < 2; mt++) {
#pragma unroll
        for (int half = 0; half < 2; half++) {
            int gr = rowbase + wm * 32 + mt * 16 + g + half * 8;
            if (gr < M) {
#pragma unroll
                for (int nt = 0; nt < 4; nt++) {
                    int gc = colbase + wn * 32 + nt * 8 + tg * 2;
                    float2 v = half ? make_float2(acc[mt][nt][2], acc[mt][nt][3])
                                    : make_float2(acc[mt][nt][0], acc[mt][nt][1]);
                    *(float2*)&C[(size_t)gr * 256 + gc] = v;
                }
            }
        }
    }
}

// ---- fused: CSR gather-reduce + self-loop + bias -> safe -> LN -> relu -> +res
// 64 threads per node (one float4/thread), 4 nodes per 256-thread block.
// NN = 100000 = 4 * 25000 exactly, no partial blocks.
__global__ __launch_bounds__(256) void k_aggpost(const float* __restrict__ bias,
                                                 const float* __restrict__ lng,
                                                 const float* __restrict__ lnb,
                                                 const float* __restrict__ hres,
                                                 float* __restrict__ out) {
    __shared__ float red[8][2];
    int grp  = threadIdx.x >> 6;
    int lane = threadIdx.x & 63;
    int node = blockIdx.x * 4 + grp;

    int s = g_rs[node], epd = g_rs[node + 1];
    float d = g_dis[node];
    float self = d * d;
    const float4* xw4 = (const float4*)g_xw;

    float4 acc;
    {
        float4 v = xw4[(size_t)node * 64 + lane];
        float4 b = ((const float4*)bias)[lane];
        acc.x = fmaf(self, v.x, b.x);
        acc.y = fmaf(self, v.y, b.y);
        acc.z = fmaf(self, v.z, b.z);
        acc.w = fmaf(self, v.w, b.w);
    }
    int i = s;
    for (; i + 1 < epd; i += 2) {
        int   s0 = g_src[i],     s1 = g_src[i + 1];
        float w0 = g_nrm[i],     w1 = g_nrm[i + 1];
        float4 v0 = xw4[(size_t)s0 * 64 + lane];
        float4 v1 = xw4[(size_t)s1 * 64 + lane];
        acc.x = fmaf(w0, v0.x, acc.x); acc.x = fmaf(w1, v1.x, acc.x);
        acc.y = fmaf(w0, v0.y, acc.y); acc.y = fmaf(w1, v1.y, acc.y);
        acc.z = fmaf(w0, v0.z, acc.z); acc.z = fmaf(w1, v1.z, acc.z);
        acc.w = fmaf(w0, v0.w, acc.w); acc.w = fmaf(w1, v1.w, acc.w);
    }
    if (i < epd) {
        int   s0 = g_src[i];
        float w0 = g_nrm[i];
        float4 v0 = xw4[(size_t)s0 * 64 + lane];
        acc.x = fmaf(w0, v0.x, acc.x);
        acc.y = fmaf(w0, v0.y, acc.y);
        acc.z = fmaf(w0, v0.z, acc.z);
        acc.w = fmaf(w0, v0.w, acc.w);
    }

    acc.x = fsafe(acc.x); acc.y = fsafe(acc.y);
    acc.z = fsafe(acc.z); acc.w = fsafe(acc.w);

    float ss = acc.x + acc.y + acc.z + acc.w;
    float sq = acc.x * acc.x + acc.y * acc.y + acc.z * acc.z + acc.w * acc.w;
#pragma unroll
    for (int o = 16; o > 0; o >>= 1) {
        ss += __shfl_xor_sync(0xFFFFFFFFu, ss, o);
        sq += __shfl_xor_sync(0xFFFFFFFFu, sq, o);
    }
    int bw = threadIdx.x >> 5;           // warp index within block (0..7)
    if ((threadIdx.x & 31) == 0) { red[bw][0] = ss; red[bw][1] = sq; }
    __syncthreads();
    int peer = bw ^ 1;
    ss = red[bw][0] + red[peer][0];
    sq = red[bw][1] + red[peer][1];

    float mu  = ss * (1.0f / 256.0f);
    float var = sq * (1.0f / 256.0f) - mu * mu;
    float inv = rsqrtf(var + LN_EPS);

    float4 gg = ((const float4*)lng)[lane];
    float4 bb = ((const float4*)lnb)[lane];
    float4 rr = ((const float4*)&hres[(size_t)node * DD])[lane];

    float4 o;
    o.x = fsafe(fmaxf(fsafe((acc.x - mu) * inv * gg.x + bb.x), 0.f) + rr.x);
    o.y = fsafe(fmaxf(fsafe((acc.y - mu) * inv * gg.y + bb.y), 0.f) + rr.y);
    o.z = fsafe(fmaxf(fsafe((acc.z - mu) * inv * gg.z + bb.z), 0.f) + rr.z);
    o.w = fsafe(fmaxf(fsafe((acc.w - mu) * inv * gg.w + bb.w), 0.f) + rr.w);

    ((float4*)&out[(size_t)node * DD])[lane] = o;
}

// ---------------- host launch ------------------------------------------------
extern "C" void kernel_launch(void* const* d_in, const int* in_sizes, int n_in,
                              void* d_out, int out_size) {
    const float* x   = (const float*)d_in[0];
    const void*  ei  = d_in[1];
    const float* ew  = (const float*)d_in[2];
    const float* W1  = (const float*)d_in[3];
    const float* b1  = (const float*)d_in[4];
    const float* lg1 = (const float*)d_in[5];
    const float* lb1 = (const float*)d_in[6];
    const float* W2  = (const float*)d_in[7];
    const float* b2  = (const float*)d_in[8];
    const float* lg2 = (const float*)d_in[9];
    const float* lb2 = (const float*)d_in[10];
    float* out = (float*)d_out;

    void *p_h = nullptr, *p_xw = nullptr;
    cudaGetSymbolAddress(&p_h, g_h);
    cudaGetSymbolAddress(&p_xw, g_xw);
    const float* h0 = (const float*)p_h;
    float* xw = (float*)p_xw;

    const long long nd4 = (long long)NN * DD / 4;

    k_detect<<<1, 1>>>(ei);
    k_zero<<<(NN + 255) / 256, 256>>>();
    k_deg<<<(EE + 255) / 256, 256>>>(ei, ew);
    k_dis<<<(NN + 255) / 256, 256>>>();
    k_scan<<<1, 1024>>>();
    k_fill<<<(EE + 255) / 256, 256>>>(ei);
    k_safe_copy<<<(int)((nd4 + 255) / 256), 256>>>(x);

    dim3 gemm_grid((NN + GBM - 1) / GBM, 256 / GBN);

    // ---- layer 1 ----
    k_gemm_tf32<<<gemm_grid, 256>>>(h0, W1, xw, NN);
    k_aggpost<<<NN / 4, 256>>>(b1, lg1, lb1, h0, out);

    // ---- layer 2 ----
    k_gemm_tf32<<<gemm_grid, 256>>>(out, W2, xw, NN);
    k_aggpost<<<NN / 4, 256>>>(b2, lg2, lb2, out, out);
}